// round 4
// baseline (speedup 1.0000x reference)
#include <cuda_runtime.h>
#include <cuda_bf16.h>
#include <math.h>
#include <stdint.h>

#define N_ENT   40000
#define N_REL   500
#define E_DIR   200000
#define E_2HOP  50000
#define E_TOT   250000

// ---------------- scratch (static device allocations; no runtime alloc) ----------------
__device__ float g_C1[(size_t)N_ENT * 768];   // [P1 | P2 | ENT]
__device__ float g_C2[(size_t)N_ENT * 512];   // [X1 | X2]
__device__ float g_R3[N_REL * 256];           // init_rel @ W3h
__device__ float g_RW[N_REL * 256];           // r @ O3
__device__ float g_B3[128 * 256];             // W3h (fp32, small SIMT gemm)
// bf16 hi/lo splits for tensor-core GEMMs
__device__ __nv_bfloat16 g_Eh[(size_t)N_ENT * 128], g_El[(size_t)N_ENT * 128];
__device__ __nv_bfloat16 g_Xh[(size_t)N_ENT * 256], g_Xl[(size_t)N_ENT * 256];
__device__ __nv_bfloat16 g_B1th[768 * 128], g_B1tl[768 * 128];     // B1^T  [N=768, K=128]
__device__ __nv_bfloat16 g_O12th[512 * 256], g_O12tl[512 * 256];   // O12^T [N=512, K=256]
__device__ float g_q1[N_ENT * 4], g_q2[N_ENT * 4];
__device__ float g_y1[N_ENT],     g_y2[N_ENT];
__device__ float g_ra[N_REL * 4], g_rwa[N_REL];
__device__ int   g_count[N_ENT + 1], g_ptr[N_ENT + 1], g_fill[N_ENT], g_eidx[E_TOT];
__device__ float g_bnsum[256], g_bnsq[256];

// ---------------- small helpers ----------------
__device__ __forceinline__ float lrelu(float x) { return x > 0.f ? x : 0.2f * x; }
__device__ __forceinline__ float elu(float x)   { return x > 0.f ? x : expm1f(x); }

__device__ __forceinline__ void bf16_split(float v, __nv_bfloat16& h, __nv_bfloat16& l) {
    h = __float2bfloat16(v);
    l = __float2bfloat16(v - __bfloat162float(h));
}

// ---------------- bf16 mma.sync + ldmatrix (baseline PTX ISA) ----------------
__device__ __forceinline__ void mma16816(float* c, const uint32_t* a, uint32_t b0, uint32_t b1) {
    asm volatile(
        "mma.sync.aligned.m16n8k16.row.col.f32.bf16.bf16.f32 "
        "{%0,%1,%2,%3}, {%4,%5,%6,%7}, {%8,%9}, {%0,%1,%2,%3};"
        : "+f"(c[0]), "+f"(c[1]), "+f"(c[2]), "+f"(c[3])
        : "r"(a[0]), "r"(a[1]), "r"(a[2]), "r"(a[3]), "r"(b0), "r"(b1));
}
__device__ __forceinline__ void ldsm4(uint32_t addr, uint32_t* r) {
    asm volatile("ldmatrix.sync.aligned.m8n8.x4.shared.b16 {%0,%1,%2,%3}, [%4];"
                 : "=r"(r[0]), "=r"(r[1]), "=r"(r[2]), "=r"(r[3]) : "r"(addr));
}

// ---------------- pipelined tensor-core GEMM: C[M,N] = A[M,K] @ Bt[N,K]^T ----------------
// fp32 emulated via bf16 hi/lo 3-pass: D = Ah*Bh + Al*Bh + Ah*Bl.
// CTA 128x128, 8 warps (4m x 2n), warp tile 32x64. K-chunk 32, 2 cp.async stages.
// Stage arrays: [Ah, Al, Bh, Bl], each 128 rows x 32 bf16, row stride 40 (no ldsm conflicts).
#define SAP 40
#define STAGE_B (128 * SAP * 2)         // 10240 bytes per array per stage
#define GSM_TOTAL (2 * 4 * STAGE_B)     // 81920 bytes

__global__ void __launch_bounds__(256)
gemm_mma(const __nv_bfloat16* __restrict__ Ah_, const __nv_bfloat16* __restrict__ Al_,
         const __nv_bfloat16* __restrict__ Bth, const __nv_bfloat16* __restrict__ Btl,
         float* __restrict__ C, int M, int N, int K) {
    extern __shared__ char smem[];
    uint32_t smb = (uint32_t)__cvta_generic_to_shared(smem);
    int tid = threadIdx.x, lane = tid & 31, wid = tid >> 5;
    int wm = wid & 3, wn = wid >> 2;
    int g = lane >> 2, tg = lane & 3;
    int mbase = blockIdx.y * 128, nbase = blockIdx.x * 128;

    float acc[2][8][4] = {};
    const int nch = K >> 5;

    auto issue = [&](int c, int s) {
        int kb = c << 5;
        uint32_t sb0 = smb + (uint32_t)(s * 4) * STAGE_B;
#pragma unroll
        for (int p = 0; p < 2; p++) {
            int idx = p * 256 + tid;
            int row = idx >> 2, ch = idx & 3;
            int gr = mbase + row;
            int ga = gr < M ? gr : (M - 1);
            int sz = gr < M ? 16 : 0;
            uint32_t d = sb0 + (uint32_t)(row * SAP + ch * 8) * 2;
            const void* s1 = &Ah_[(size_t)ga * K + kb + ch * 8];
            const void* s2 = &Al_[(size_t)ga * K + kb + ch * 8];
            asm volatile("cp.async.cg.shared.global [%0], [%1], 16, %2;" :: "r"(d), "l"(s1), "r"(sz));
            asm volatile("cp.async.cg.shared.global [%0], [%1], 16, %2;" :: "r"(d + STAGE_B), "l"(s2), "r"(sz));
        }
#pragma unroll
        for (int p = 0; p < 2; p++) {
            int idx = p * 256 + tid;
            int row = idx >> 2, ch = idx & 3;
            uint32_t d = sb0 + 2 * STAGE_B + (uint32_t)(row * SAP + ch * 8) * 2;
            const void* s1 = &Bth[(size_t)(nbase + row) * K + kb + ch * 8];
            const void* s2 = &Btl[(size_t)(nbase + row) * K + kb + ch * 8];
            asm volatile("cp.async.cg.shared.global [%0], [%1], 16;" :: "r"(d), "l"(s1));
            asm volatile("cp.async.cg.shared.global [%0], [%1], 16;" :: "r"(d + STAGE_B), "l"(s2));
        }
    };

    issue(0, 0);
    asm volatile("cp.async.commit_group;" ::: "memory");

    for (int c = 0; c < nch; c++) {
        int s = c & 1;
        if (c + 1 < nch) {
            issue(c + 1, 1 - s);
            asm volatile("cp.async.commit_group;" ::: "memory");
            asm volatile("cp.async.wait_group 1;" ::: "memory");
        } else {
            asm volatile("cp.async.wait_group 0;" ::: "memory");
        }
        __syncthreads();

        uint32_t offA = smb + (uint32_t)(s * 4) * STAGE_B;
        uint32_t offB = offA + 2 * STAGE_B;
#pragma unroll
        for (int ks = 0; ks < 2; ks++) {
            int k0 = ks << 4;
            uint32_t ah[2][4], al[2][4], bh[4][4], bl[4][4];
            int arow = wm * 32 + (lane & 15);
            int acol = k0 + ((lane >> 4) << 3);
#pragma unroll
            for (int mt = 0; mt < 2; mt++) {
                uint32_t ad = offA + (uint32_t)((arow + mt * 16) * SAP + acol) * 2;
                ldsm4(ad, ah[mt]);
                ldsm4(ad + STAGE_B, al[mt]);
            }
            int brow = wn * 64 + (lane & 7) + ((lane >> 4) << 3);
            int bcol = k0 + (((lane >> 3) & 1) << 3);
#pragma unroll
            for (int nt2 = 0; nt2 < 4; nt2++) {
                uint32_t bd = offB + (uint32_t)((brow + nt2 * 16) * SAP + bcol) * 2;
                ldsm4(bd, bh[nt2]);
                ldsm4(bd + STAGE_B, bl[nt2]);
            }
#pragma unroll
            for (int mt = 0; mt < 2; mt++)
#pragma unroll
                for (int nt = 0; nt < 8; nt++) {
                    int n2 = nt >> 1, hf = (nt & 1) * 2;
                    mma16816(acc[mt][nt], ah[mt], bh[n2][hf], bh[n2][hf + 1]);
                    mma16816(acc[mt][nt], al[mt], bh[n2][hf], bh[n2][hf + 1]);
                    mma16816(acc[mt][nt], ah[mt], bl[n2][hf], bl[n2][hf + 1]);
                }
        }
        __syncthreads();
    }

    // epilogue
#pragma unroll
    for (int mt = 0; mt < 2; mt++) {
        int r0 = mbase + wm * 32 + mt * 16 + g;
#pragma unroll
        for (int nt = 0; nt < 8; nt++) {
            int c0 = nbase + wn * 64 + nt * 8 + tg * 2;
            if (r0 < M) {
                C[(size_t)r0 * N + c0]     = acc[mt][nt][0];
                C[(size_t)r0 * N + c0 + 1] = acc[mt][nt][1];
            }
            if (r0 + 8 < M) {
                C[(size_t)(r0 + 8) * N + c0]     = acc[mt][nt][2];
                C[(size_t)(r0 + 8) * N + c0 + 1] = acc[mt][nt][3];
            }
        }
    }
}

// ---------------- zero scratch ----------------
__global__ void zero_kernel() {
    int i = blockIdx.x * blockDim.x + threadIdx.x;
    if (i <= N_ENT) g_count[i] = 0;
    if (i <  N_ENT) g_fill[i]  = 0;
    if (i < 256) { g_bnsum[i] = 0.f; g_bnsq[i] = 0.f; }
}

// ---------------- split embed to bf16 hi/lo ----------------
__global__ void split_embed_kernel(const float* __restrict__ e) {
    int i = blockIdx.x * blockDim.x + threadIdx.x;
    if (i >= N_ENT * 128) return;
    __nv_bfloat16 h, l;
    bf16_split(e[i], h, l);
    g_Eh[i] = h; g_El[i] = l;
}

// ---------------- assemble weight blocks (transposed bf16 splits + fp32 B3) ----------------
__global__ void assemble_kernel(const float* __restrict__ Wh, const float* __restrict__ Went,
                                const float* __restrict__ outW) {
    int i = blockIdx.x * blockDim.x + threadIdx.x;
    const int NB1 = 768 * 128, NB3 = 128 * 256, NO = 512 * 256;
    if (i < NB1) {
        int c = i / 128, d = i % 128;   // B1t[c][d] = B1[d][c]
        float v;
        if (c < 256)      { int h = c >> 6, k = c & 63; v = Wh[h * 24576 + d * 64 + k]; }
        else if (c < 512) { int cc = c - 256; int h = cc >> 6, k = cc & 63; v = Wh[h * 24576 + (128 + d) * 64 + k]; }
        else              { v = Went[d * 256 + (c - 512)]; }
        __nv_bfloat16 hh, ll; bf16_split(v, hh, ll);
        g_B1th[i] = hh; g_B1tl[i] = ll;
    } else if (i < NB1 + NB3) {
        int j = i - NB1; int d = j / 256, cc = j % 256;
        int h = cc >> 6, k = cc & 63;
        g_B3[j] = Wh[h * 24576 + (256 + d) * 64 + k];
    } else if (i < NB1 + NB3 + NO) {
        int j = i - NB1 - NB3; int c = j / 256, k = j % 256;  // O12t[c][k] = O12[k][c]
        float v = (c < 256) ? outW[k * 256 + c] : outW[(256 + k) * 256 + (c - 256)];
        __nv_bfloat16 hh, ll; bf16_split(v, hh, ll);
        g_O12th[j] = hh; g_O12tl[j] = ll;
    }
}

// ---------------- small fp32 SGEMM (relation-space only) ----------------
__global__ __launch_bounds__(256) void sgemm(const float* __restrict__ A,
                                             const float* __restrict__ B,
                                             float* __restrict__ C,
                                             int M, int N, int K) {
    __shared__ float As[16][68];
    __shared__ float Bs[16][64];
    int tid = threadIdx.x;
    int tr = tid >> 4, tc = tid & 15;
    int rowbase = blockIdx.y * 64, colbase = blockIdx.x * 64;
    float acc[4][4] = {};
    for (int k0 = 0; k0 < K; k0 += 16) {
#pragma unroll
        for (int p = 0; p < 4; p++) {
            int r = p * 16 + (tid >> 4), cc = tid & 15;
            int gr = rowbase + r;
            As[cc][r] = (gr < M) ? A[(size_t)gr * K + k0 + cc] : 0.f;
        }
#pragma unroll
        for (int p = 0; p < 4; p++) {
            int r = p * 4 + (tid >> 6), cc = tid & 63;
            Bs[r][cc] = B[(size_t)(k0 + r) * N + colbase + cc];
        }
        __syncthreads();
#pragma unroll
        for (int k = 0; k < 16; k++) {
            float a0 = As[k][tr * 4 + 0], a1 = As[k][tr * 4 + 1];
            float a2 = As[k][tr * 4 + 2], a3 = As[k][tr * 4 + 3];
            float4 b = *(const float4*)&Bs[k][tc * 4];
            acc[0][0] += a0 * b.x; acc[0][1] += a0 * b.y; acc[0][2] += a0 * b.z; acc[0][3] += a0 * b.w;
            acc[1][0] += a1 * b.x; acc[1][1] += a1 * b.y; acc[1][2] += a1 * b.z; acc[1][3] += a1 * b.w;
            acc[2][0] += a2 * b.x; acc[2][1] += a2 * b.y; acc[2][2] += a2 * b.z; acc[2][3] += a2 * b.w;
            acc[3][0] += a3 * b.x; acc[3][1] += a3 * b.y; acc[3][2] += a3 * b.z; acc[3][3] += a3 * b.w;
        }
        __syncthreads();
    }
#pragma unroll
    for (int i = 0; i < 4; i++) {
        int gr = rowbase + tr * 4 + i;
        if (gr < M) {
#pragma unroll
            for (int j = 0; j < 4; j++)
                C[(size_t)gr * N + colbase + tc * 4 + j] = acc[i][j];
        }
    }
}

// ---------------- CSR build ----------------
__device__ __forceinline__ int edge_row(int e, const int* ei, const int* i2) {
    return (e < E_DIR) ? ei[E_DIR + e] : i2[(e - E_DIR) * 4 + 3];
}

__global__ void hist_kernel(const int* __restrict__ ei, const int* __restrict__ i2) {
    int e = blockIdx.x * blockDim.x + threadIdx.x;
    if (e >= E_TOT) return;
    atomicAdd(&g_count[edge_row(e, ei, i2)], 1);
}

// single block, 1024 threads, 40 contiguous counts per thread
__global__ void scan_kernel() {
    __shared__ int s[1024];
    const int CH = 40;
    int t = threadIdx.x;
    int base = t * CH;
    int sum = 0;
    for (int j = 0; j < CH; j++) {
        int i = base + j;
        sum += (i < N_ENT) ? g_count[i] : 0;
    }
    s[t] = sum;
    __syncthreads();
    for (int off = 1; off < 1024; off <<= 1) {
        int add = (t >= off) ? s[t - off] : 0;
        __syncthreads();
        s[t] += add;
        __syncthreads();
    }
    int run = s[t] - sum;
    for (int j = 0; j < CH; j++) {
        int i = base + j;
        if (i < N_ENT) {
            g_ptr[i] = run;
            run += g_count[i];
        }
    }
    if (t == 1023) g_ptr[N_ENT] = s[1023];
}

__global__ void scatter_kernel(const int* __restrict__ ei, const int* __restrict__ i2) {
    int e = blockIdx.x * blockDim.x + threadIdx.x;
    if (e >= E_TOT) return;
    int row = edge_row(e, ei, i2);
    int pos = g_ptr[row] + atomicAdd(&g_fill[row], 1);
    g_eidx[pos] = e;
}

// ---------------- per-entity / per-relation attention scalars ----------------
__global__ void qkern(const float* __restrict__ a_heads) {
    int w = (blockIdx.x * blockDim.x + threadIdx.x) >> 5;
    int lane = threadIdx.x & 31;
    if (w >= N_ENT) return;
    const float* base = &g_C1[(size_t)w * 768];
    float s1 = 0.f, s2 = 0.f;
#pragma unroll
    for (int j = 0; j < 8; j++) {
        float av = a_heads[lane * 8 + j];
        s1 += base[lane * 8 + j] * av;
        s2 += base[256 + lane * 8 + j] * av;
    }
    for (int o = 4; o; o >>= 1) {
        s1 += __shfl_xor_sync(0xffffffffu, s1, o);
        s2 += __shfl_xor_sync(0xffffffffu, s2, o);
    }
    if ((lane & 7) == 0) {
        g_q1[w * 4 + (lane >> 3)] = s1;
        g_q2[w * 4 + (lane >> 3)] = s2;
    }
}

__global__ void rakern(const float* __restrict__ a_heads) {
    int w = (blockIdx.x * blockDim.x + threadIdx.x) >> 5;
    int lane = threadIdx.x & 31;
    if (w >= N_REL) return;
    const float* base = &g_R3[w * 256];
    float s = 0.f;
#pragma unroll
    for (int j = 0; j < 8; j++) s += base[lane * 8 + j] * a_heads[lane * 8 + j];
    for (int o = 4; o; o >>= 1) s += __shfl_xor_sync(0xffffffffu, s, o);
    if ((lane & 7) == 0) g_ra[w * 4 + (lane >> 3)] = s;
}

__global__ void ykern(const float* __restrict__ out_a) {
    int w = (blockIdx.x * blockDim.x + threadIdx.x) >> 5;
    int lane = threadIdx.x & 31;
    if (w >= N_ENT) return;
    const float* base = &g_C2[(size_t)w * 512];
    float s1 = 0.f, s2 = 0.f;
#pragma unroll
    for (int j = 0; j < 8; j++) {
        float av = out_a[lane * 8 + j];
        s1 += base[lane * 8 + j] * av;
        s2 += base[256 + lane * 8 + j] * av;
    }
    for (int o = 16; o; o >>= 1) {
        s1 += __shfl_xor_sync(0xffffffffu, s1, o);
        s2 += __shfl_xor_sync(0xffffffffu, s2, o);
    }
    if (lane == 0) { g_y1[w] = s1; g_y2[w] = s2; }
}

__global__ void rwakern(const float* __restrict__ out_a) {
    int w = (blockIdx.x * blockDim.x + threadIdx.x) >> 5;
    int lane = threadIdx.x & 31;
    if (w >= N_REL) return;
    const float* base = &g_RW[w * 256];
    float s = 0.f;
#pragma unroll
    for (int j = 0; j < 8; j++) s += base[lane * 8 + j] * out_a[lane * 8 + j];
    for (int o = 16; o; o >>= 1) s += __shfl_xor_sync(0xffffffffu, s, o);
    if (lane == 0) g_rwa[w] = s;
}

// ---------------- layer-1 attention aggregation (no max pass: softmax shift-invariant) ----------------
__global__ __launch_bounds__(256) void agg1_kernel(const int* __restrict__ ei,
                                                   const int* __restrict__ et,
                                                   const int* __restrict__ i2) {
    int warp = blockIdx.x * 8 + (threadIdx.x >> 5);
    int lane = threadIdx.x & 31;
    if (warp >= N_ENT) return;
    int row = warp;
    int beg = g_ptr[row], end = g_ptr[row + 1];

    int hl = lane >> 3;
    int off = lane * 8;
    float qh = g_q1[row * 4 + hl];

    float acc[8] = {0, 0, 0, 0, 0, 0, 0, 0};
    float S = 0.f;
    for (int i = beg; i < end; i++) {
        int e = g_eidx[i];
        int col, a, b, dir;
        if (e < E_DIR) { col = ei[e]; a = et[e]; b = 0; dir = 1; }
        else { int j = e - E_DIR; col = i2[j * 4]; a = i2[j * 4 + 1]; b = i2[j * 4 + 2]; dir = 0; }
        float ras = g_ra[a * 4 + hl] + (dir ? 0.f : g_ra[b * 4 + hl]);
        float l = lrelu(qh + g_q2[col * 4 + hl] + ras);
        float w = expf(l);
        S += w;
        const float* p2 = &g_C1[(size_t)col * 768 + 256 + off];
        float4 v0 = *(const float4*)p2, v1 = *(const float4*)(p2 + 4);
        const float* rr = &g_R3[a * 256 + off];
        float4 r0 = *(const float4*)rr, r1 = *(const float4*)(rr + 4);
        if (!dir) {
            const float* r2p = &g_R3[b * 256 + off];
            float4 s0 = *(const float4*)r2p, s1 = *(const float4*)(r2p + 4);
            r0.x += s0.x; r0.y += s0.y; r0.z += s0.z; r0.w += s0.w;
            r1.x += s1.x; r1.y += s1.y; r1.z += s1.z; r1.w += s1.w;
        }
        acc[0] += w * (v0.x + r0.x); acc[1] += w * (v0.y + r0.y);
        acc[2] += w * (v0.z + r0.z); acc[3] += w * (v0.w + r0.w);
        acc[4] += w * (v1.x + r1.x); acc[5] += w * (v1.y + r1.y);
        acc[6] += w * (v1.z + r1.z); acc[7] += w * (v1.w + r1.w);
    }

    const float* p1 = &g_C1[(size_t)row * 768 + off];
    float inv = 1.f / (S + 1e-16f);
#pragma unroll
    for (int j = 0; j < 8; j++) {
        float v = elu((S * p1[j] + acc[j]) * inv);
        __nv_bfloat16 h, l;
        bf16_split(v, h, l);
        g_Xh[(size_t)row * 256 + off + j] = h;
        g_Xl[(size_t)row * 256 + off + j] = l;
    }
}

// ---------------- layer-2 attention aggregation (no max pass) ----------------
__global__ __launch_bounds__(256) void agg2_kernel(const int* __restrict__ ei,
                                                   const int* __restrict__ et,
                                                   const int* __restrict__ i2,
                                                   float* __restrict__ out) {
    int warp = blockIdx.x * 8 + (threadIdx.x >> 5);
    int lane = threadIdx.x & 31;
    if (warp >= N_ENT) return;
    int row = warp;
    int beg = g_ptr[row], end = g_ptr[row + 1];
    float y1r = g_y1[row];

    int off = lane * 8;
    float acc[8] = {0, 0, 0, 0, 0, 0, 0, 0};
    float S = 0.f;
    for (int i = beg; i < end; i++) {
        int e = g_eidx[i];
        int col, a, b, dir;
        if (e < E_DIR) { col = ei[e]; a = et[e]; b = 0; dir = 1; }
        else { int j = e - E_DIR; col = i2[j * 4]; a = i2[j * 4 + 1]; b = i2[j * 4 + 2]; dir = 0; }
        float rs = g_rwa[a] + (dir ? 0.f : g_rwa[b]);
        float l = lrelu(y1r + g_y2[col] + rs);
        float w = expf(l);
        S += w;
        const float* x2 = &g_C2[(size_t)col * 512 + 256 + off];
        float4 v0 = *(const float4*)x2, v1 = *(const float4*)(x2 + 4);
        const float* rr = &g_RW[a * 256 + off];
        float4 r0 = *(const float4*)rr, r1 = *(const float4*)(rr + 4);
        if (!dir) {
            const float* r2p = &g_RW[b * 256 + off];
            float4 s0 = *(const float4*)r2p, s1 = *(const float4*)(r2p + 4);
            r0.x += s0.x; r0.y += s0.y; r0.z += s0.z; r0.w += s0.w;
            r1.x += s1.x; r1.y += s1.y; r1.z += s1.z; r1.w += s1.w;
        }
        acc[0] += w * (v0.x + r0.x); acc[1] += w * (v0.y + r0.y);
        acc[2] += w * (v0.z + r0.z); acc[3] += w * (v0.w + r0.w);
        acc[4] += w * (v1.x + r1.x); acc[5] += w * (v1.y + r1.y);
        acc[6] += w * (v1.z + r1.z); acc[7] += w * (v1.w + r1.w);
    }

    const float* x1 = &g_C2[(size_t)row * 512 + off];
    const float* ent = &g_C1[(size_t)row * 768 + 512 + off];
    float inv = 1.f / (S + 1e-16f);
#pragma unroll
    for (int j = 0; j < 8; j++) {
        float v = (S * x1[j] + acc[j]) * inv;
        out[(size_t)row * 256 + off + j] = elu(v) + ent[j];
    }
}

// ---------------- batch norm ----------------
__global__ void bnstats_kernel(const float* __restrict__ xo) {
    int c = threadIdx.x;
    float s = 0.f, s2 = 0.f;
    for (int row = blockIdx.x; row < N_ENT; row += gridDim.x) {
        float v = xo[(size_t)row * 256 + c];
        s += v; s2 += v * v;
    }
    atomicAdd(&g_bnsum[c], s);
    atomicAdd(&g_bnsq[c], s2);
}

__global__ void bnnorm_kernel(float* __restrict__ xo,
                              const float* __restrict__ gamma,
                              const float* __restrict__ beta) {
    size_t i = (size_t)blockIdx.x * blockDim.x + threadIdx.x;
    if (i >= (size_t)N_ENT * 256) return;
    int c = (int)(i & 255);
    float mu = g_bnsum[c] * (1.f / N_ENT);
    float var = g_bnsq[c] * (1.f / N_ENT) - mu * mu;
    float istd = rsqrtf(var + 1e-5f);
    float v = xo[i];
    xo[i] = (v - mu) * istd * gamma[c] + beta[c];
}

// ---------------- launch ----------------
extern "C" void kernel_launch(void* const* d_in, const int* in_sizes, int n_in,
                              void* d_out, int out_size) {
    const int*   edge_index = (const int*)d_in[0];
    const int*   edge_type  = (const int*)d_in[1];
    const int*   i2         = (const int*)d_in[2];
    const float* init_embed = (const float*)d_in[3];
    const float* init_rel   = (const float*)d_in[4];
    const float* W_heads    = (const float*)d_in[5];
    const float* a_heads    = (const float*)d_in[6];
    const float* gat_W      = (const float*)d_in[7];
    const float* out_W      = (const float*)d_in[8];
    const float* out_a      = (const float*)d_in[9];
    const float* W_ent      = (const float*)d_in[10];
    const float* gamma      = (const float*)d_in[11];
    const float* beta       = (const float*)d_in[12];

    float* out   = (float*)d_out;
    float* r_out = out + (size_t)N_ENT * 256;

    float *pC1, *pC2, *pR3, *pRW, *pB3;
    __nv_bfloat16 *pEh, *pEl, *pXh, *pXl, *pB1th, *pB1tl, *pO12th, *pO12tl;
    cudaGetSymbolAddress((void**)&pC1,    g_C1);
    cudaGetSymbolAddress((void**)&pC2,    g_C2);
    cudaGetSymbolAddress((void**)&pR3,    g_R3);
    cudaGetSymbolAddress((void**)&pRW,    g_RW);
    cudaGetSymbolAddress((void**)&pB3,    g_B3);
    cudaGetSymbolAddress((void**)&pEh,    g_Eh);
    cudaGetSymbolAddress((void**)&pEl,    g_El);
    cudaGetSymbolAddress((void**)&pXh,    g_Xh);
    cudaGetSymbolAddress((void**)&pXl,    g_Xl);
    cudaGetSymbolAddress((void**)&pB1th,  g_B1th);
    cudaGetSymbolAddress((void**)&pB1tl,  g_B1tl);
    cudaGetSymbolAddress((void**)&pO12th, g_O12th);
    cudaGetSymbolAddress((void**)&pO12tl, g_O12tl);

    static bool attr_set = false;
    if (!attr_set) {
        cudaFuncSetAttribute(gemm_mma, cudaFuncAttributeMaxDynamicSharedMemorySize, GSM_TOTAL);
        attr_set = true;
    }

    zero_kernel<<<(N_ENT + 256) / 256, 256>>>();
    split_embed_kernel<<<(N_ENT * 128 + 255) / 256, 256>>>(init_embed);
    assemble_kernel<<<(768 * 128 + 128 * 256 + 512 * 256 + 255) / 256, 256>>>(W_heads, W_ent, out_W);

    // CSR build
    hist_kernel<<<(E_TOT + 255) / 256, 256>>>(edge_index, i2);
    scan_kernel<<<1, 1024>>>();
    scatter_kernel<<<(E_TOT + 255) / 256, 256>>>(edge_index, i2);

    // big GEMM 1: C1[40000,768] = embed[40000,128] @ B1
    gemm_mma<<<dim3(768 / 128, (N_ENT + 127) / 128), 256, GSM_TOTAL>>>(pEh, pEl, pB1th, pB1tl, pC1, N_ENT, 768, 128);
    // small relation GEMMs (fp32 SIMT)
    sgemm<<<dim3(256 / 64, (N_REL + 63) / 64), 256>>>(init_rel, pB3, pR3, N_REL, 256, 128);
    sgemm<<<dim3(256 / 64, (N_REL + 63) / 64), 256>>>(init_rel, gat_W, r_out, N_REL, 256, 128);

    // layer-1 scalars + aggregation (writes Xh/Xl bf16 splits)
    qkern<<<(N_ENT * 32 + 255) / 256, 256>>>(a_heads);
    rakern<<<(N_REL * 32 + 255) / 256, 256>>>(a_heads);
    agg1_kernel<<<N_ENT / 8, 256>>>(edge_index, edge_type, i2);

    // big GEMM 2: C2[40000,512] = X[40000,256] @ O12
    gemm_mma<<<dim3(512 / 128, (N_ENT + 127) / 128), 256, GSM_TOTAL>>>(pXh, pXl, pO12th, pO12tl, pC2, N_ENT, 512, 256);
    sgemm<<<dim3(256 / 64, (N_REL + 63) / 64), 256>>>(r_out, out_W + 512 * 256, pRW, N_REL, 256, 256);
    ykern<<<(N_ENT * 32 + 255) / 256, 256>>>(out_a);
    rwakern<<<(N_REL * 32 + 255) / 256, 256>>>(out_a);
    agg2_kernel<<<N_ENT / 8, 256>>>(edge_index, edge_type, i2, out);

    // batch norm
    bnstats_kernel<<<512, 256>>>(out);
    bnnorm_kernel<<<(N_ENT * 256 + 255) / 256, 256>>>(out, gamma, beta);
}

// round 6
// speedup vs baseline: 1.5033x; 1.5033x over previous
#include <cuda_runtime.h>
#include <cuda_bf16.h>
#include <math.h>
#include <stdint.h>

#define N_ENT   40000
#define N_REL   500
#define E_DIR   200000
#define E_2HOP  50000
#define E_TOT   250000

// ---------------- scratch (static device allocations; no runtime alloc) ----------------
__device__ float g_C1[(size_t)N_ENT * 768];   // [P1 | P2 | ENT]
__device__ float g_C2[(size_t)N_ENT * 512];   // [X1 | X2]
__device__ float g_R3[N_REL * 256];           // init_rel @ W3h
__device__ float g_RW[N_REL * 256];           // r @ O3
__device__ float g_B3[128 * 256];             // W3h (fp32, small SIMT gemm)
// bf16 hi/lo splits for tensor-core GEMMs
__device__ __nv_bfloat16 g_Eh[(size_t)N_ENT * 128], g_El[(size_t)N_ENT * 128];
__device__ __nv_bfloat16 g_Xh[(size_t)N_ENT * 256], g_Xl[(size_t)N_ENT * 256];
__device__ __nv_bfloat16 g_B1th[768 * 128], g_B1tl[768 * 128];     // B1^T  [N=768, K=128]
__device__ __nv_bfloat16 g_O12th[512 * 256], g_O12tl[512 * 256];   // O12^T [N=512, K=256]
__device__ float g_q1[N_ENT * 4], g_q2[N_ENT * 4];
__device__ float g_y1[N_ENT],     g_y2[N_ENT];
__device__ float g_ra[N_REL * 4], g_rwa[N_REL];
__device__ int   g_count[N_ENT + 1], g_ptr[N_ENT + 1], g_fill[N_ENT], g_eidx[E_TOT];
__device__ float g_bnsum[256], g_bnsq[256];

// ---------------- small helpers ----------------
__device__ __forceinline__ float lrelu(float x) { return x > 0.f ? x : 0.2f * x; }
__device__ __forceinline__ float elu(float x)   { return x > 0.f ? x : expm1f(x); }

__device__ __forceinline__ void bf16_split(float v, __nv_bfloat16& h, __nv_bfloat16& l) {
    h = __float2bfloat16(v);
    l = __float2bfloat16(v - __bfloat162float(h));
}

// ---------------- bf16 mma.sync (legacy tensor-core path, baseline PTX ISA) ----------------
__device__ __forceinline__ void mma16816(float* c, const uint32_t* a, const uint32_t* b) {
    asm volatile(
        "mma.sync.aligned.m16n8k16.row.col.f32.bf16.bf16.f32 "
        "{%0,%1,%2,%3}, {%4,%5,%6,%7}, {%8,%9}, {%0,%1,%2,%3};"
        : "+f"(c[0]), "+f"(c[1]), "+f"(c[2]), "+f"(c[3])
        : "r"(a[0]), "r"(a[1]), "r"(a[2]), "r"(a[3]), "r"(b[0]), "r"(b[1]));
}

// ---------------- tensor-core GEMM: C[M,N] = A[M,K] @ Bt[N,K]^T  (round-3 known-good) ----------------
// fp32 emulated via bf16 hi/lo 3-pass: D = Ah*Bh + Al*Bh + Ah*Bl.
// CTA: 128x128 tile, 8 warps in 4(m) x 2(n); warp tile 32x64 = 2x8 m16n8k16 tiles.
// K chunk = 64 per smem stage. Row pad 72 bf16 (144B) to break bank conflicts.
#define GP 72
#define GTILE_B (128 * GP * 2)          // 18432 bytes per tile
#define GSM_TOTAL (4 * GTILE_B)         // 73728 bytes

__global__ void __launch_bounds__(256, 1)
gemm_mma(const __nv_bfloat16* __restrict__ Ah, const __nv_bfloat16* __restrict__ Al,
         const __nv_bfloat16* __restrict__ Bth, const __nv_bfloat16* __restrict__ Btl,
         float* __restrict__ C, int M, int N, int K) {
    extern __shared__ char smem[];
    __nv_bfloat16* sAh = (__nv_bfloat16*)(smem);
    __nv_bfloat16* sAl = (__nv_bfloat16*)(smem + GTILE_B);
    __nv_bfloat16* sBh = (__nv_bfloat16*)(smem + 2 * GTILE_B);
    __nv_bfloat16* sBl = (__nv_bfloat16*)(smem + 3 * GTILE_B);

    int tid = threadIdx.x, wid = tid >> 5, lane = tid & 31;
    int wm = wid & 3, wn = wid >> 2;          // warp position: 4 x 2
    int g = lane >> 2, tg = lane & 3;         // mma fragment mapping
    int mbase = blockIdx.y * 128, nbase = blockIdx.x * 128;

    float acc[2][8][4];
#pragma unroll
    for (int mt = 0; mt < 2; mt++)
#pragma unroll
        for (int nt = 0; nt < 8; nt++)
#pragma unroll
            for (int q = 0; q < 4; q++) acc[mt][nt][q] = 0.f;

    for (int kb = 0; kb < K; kb += 64) {
        // load A tiles (128 x 64), guarded + zero-padded beyond M
#pragma unroll
        for (int p = 0; p < 4; p++) {
            int idx = p * 256 + tid;          // 1024 uint4 slots per tile
            int r = idx >> 3, c8 = (idx & 7) << 3;
            int gr = mbase + r;
            uint4 vh = make_uint4(0, 0, 0, 0), vl = make_uint4(0, 0, 0, 0);
            if (gr < M) {
                vh = *(const uint4*)&Ah[(size_t)gr * K + kb + c8];
                vl = *(const uint4*)&Al[(size_t)gr * K + kb + c8];
            }
            *(uint4*)&sAh[r * GP + c8] = vh;
            *(uint4*)&sAl[r * GP + c8] = vl;
        }
        // load B tiles (128 x 64); N is a multiple of 128
#pragma unroll
        for (int p = 0; p < 4; p++) {
            int idx = p * 256 + tid;
            int r = idx >> 3, c8 = (idx & 7) << 3;
            *(uint4*)&sBh[r * GP + c8] = *(const uint4*)&Bth[(size_t)(nbase + r) * K + kb + c8];
            *(uint4*)&sBl[r * GP + c8] = *(const uint4*)&Btl[(size_t)(nbase + r) * K + kb + c8];
        }
        __syncthreads();

#pragma unroll
        for (int ks = 0; ks < 4; ks++) {
            int kc = ks * 16;
            uint32_t ah[2][4], al[2][4], bh[8][2], bl[8][2];
#pragma unroll
            for (int mt = 0; mt < 2; mt++) {
                int r0 = wm * 32 + mt * 16 + g;
                ah[mt][0] = *(const uint32_t*)&sAh[r0 * GP + kc + tg * 2];
                ah[mt][1] = *(const uint32_t*)&sAh[(r0 + 8) * GP + kc + tg * 2];
                ah[mt][2] = *(const uint32_t*)&sAh[r0 * GP + kc + 8 + tg * 2];
                ah[mt][3] = *(const uint32_t*)&sAh[(r0 + 8) * GP + kc + 8 + tg * 2];
                al[mt][0] = *(const uint32_t*)&sAl[r0 * GP + kc + tg * 2];
                al[mt][1] = *(const uint32_t*)&sAl[(r0 + 8) * GP + kc + tg * 2];
                al[mt][2] = *(const uint32_t*)&sAl[r0 * GP + kc + 8 + tg * 2];
                al[mt][3] = *(const uint32_t*)&sAl[(r0 + 8) * GP + kc + 8 + tg * 2];
            }
#pragma unroll
            for (int nt = 0; nt < 8; nt++) {
                int n0 = wn * 64 + nt * 8 + g;
                bh[nt][0] = *(const uint32_t*)&sBh[n0 * GP + kc + tg * 2];
                bh[nt][1] = *(const uint32_t*)&sBh[n0 * GP + kc + 8 + tg * 2];
                bl[nt][0] = *(const uint32_t*)&sBl[n0 * GP + kc + tg * 2];
                bl[nt][1] = *(const uint32_t*)&sBl[n0 * GP + kc + 8 + tg * 2];
            }
#pragma unroll
            for (int mt = 0; mt < 2; mt++)
#pragma unroll
                for (int nt = 0; nt < 8; nt++) {
                    mma16816(acc[mt][nt], ah[mt], bh[nt]);
                    mma16816(acc[mt][nt], al[mt], bh[nt]);
                    mma16816(acc[mt][nt], ah[mt], bl[nt]);
                }
        }
        __syncthreads();
    }

    // epilogue
#pragma unroll
    for (int mt = 0; mt < 2; mt++) {
        int r0 = mbase + wm * 32 + mt * 16 + g;
#pragma unroll
        for (int nt = 0; nt < 8; nt++) {
            int c0 = nbase + wn * 64 + nt * 8 + tg * 2;
            if (r0 < M) {
                C[(size_t)r0 * N + c0]     = acc[mt][nt][0];
                C[(size_t)r0 * N + c0 + 1] = acc[mt][nt][1];
            }
            if (r0 + 8 < M) {
                C[(size_t)(r0 + 8) * N + c0]     = acc[mt][nt][2];
                C[(size_t)(r0 + 8) * N + c0 + 1] = acc[mt][nt][3];
            }
        }
    }
}

// ---------------- zero scratch ----------------
__global__ void zero_kernel() {
    int i = blockIdx.x * blockDim.x + threadIdx.x;
    if (i <= N_ENT) g_count[i] = 0;
    if (i <  N_ENT) g_fill[i]  = 0;
    if (i < 256) { g_bnsum[i] = 0.f; g_bnsq[i] = 0.f; }
}

// ---------------- split embed to bf16 hi/lo ----------------
__global__ void split_embed_kernel(const float* __restrict__ e) {
    int i = blockIdx.x * blockDim.x + threadIdx.x;
    if (i >= N_ENT * 128) return;
    __nv_bfloat16 h, l;
    bf16_split(e[i], h, l);
    g_Eh[i] = h; g_El[i] = l;
}

// ---------------- assemble weight blocks (transposed bf16 splits + fp32 B3) ----------------
__global__ void assemble_kernel(const float* __restrict__ Wh, const float* __restrict__ Went,
                                const float* __restrict__ outW) {
    int i = blockIdx.x * blockDim.x + threadIdx.x;
    const int NB1 = 768 * 128, NB3 = 128 * 256, NO = 512 * 256;
    if (i < NB1) {
        int c = i / 128, d = i % 128;   // B1t[c][d] = B1[d][c]
        float v;
        if (c < 256)      { int h = c >> 6, k = c & 63; v = Wh[h * 24576 + d * 64 + k]; }
        else if (c < 512) { int cc = c - 256; int h = cc >> 6, k = cc & 63; v = Wh[h * 24576 + (128 + d) * 64 + k]; }
        else              { v = Went[d * 256 + (c - 512)]; }
        __nv_bfloat16 hh, ll; bf16_split(v, hh, ll);
        g_B1th[i] = hh; g_B1tl[i] = ll;
    } else if (i < NB1 + NB3) {
        int j = i - NB1; int d = j / 256, cc = j % 256;
        int h = cc >> 6, k = cc & 63;
        g_B3[j] = Wh[h * 24576 + (256 + d) * 64 + k];
    } else if (i < NB1 + NB3 + NO) {
        int j = i - NB1 - NB3; int c = j / 256, k = j % 256;  // O12t[c][k] = O12[k][c]
        float v = (c < 256) ? outW[k * 256 + c] : outW[(256 + k) * 256 + (c - 256)];
        __nv_bfloat16 hh, ll; bf16_split(v, hh, ll);
        g_O12th[j] = hh; g_O12tl[j] = ll;
    }
}

// ---------------- small fp32 SGEMM (relation-space only) ----------------
__global__ __launch_bounds__(256) void sgemm(const float* __restrict__ A,
                                             const float* __restrict__ B,
                                             float* __restrict__ C,
                                             int M, int N, int K) {
    __shared__ float As[16][68];
    __shared__ float Bs[16][64];
    int tid = threadIdx.x;
    int tr = tid >> 4, tc = tid & 15;
    int rowbase = blockIdx.y * 64, colbase = blockIdx.x * 64;
    float acc[4][4] = {};
    for (int k0 = 0; k0 < K; k0 += 16) {
#pragma unroll
        for (int p = 0; p < 4; p++) {
            int r = p * 16 + (tid >> 4), cc = tid & 15;
            int gr = rowbase + r;
            As[cc][r] = (gr < M) ? A[(size_t)gr * K + k0 + cc] : 0.f;
        }
#pragma unroll
        for (int p = 0; p < 4; p++) {
            int r = p * 4 + (tid >> 6), cc = tid & 63;
            Bs[r][cc] = B[(size_t)(k0 + r) * N + colbase + cc];
        }
        __syncthreads();
#pragma unroll
        for (int k = 0; k < 16; k++) {
            float a0 = As[k][tr * 4 + 0], a1 = As[k][tr * 4 + 1];
            float a2 = As[k][tr * 4 + 2], a3 = As[k][tr * 4 + 3];
            float4 b = *(const float4*)&Bs[k][tc * 4];
            acc[0][0] += a0 * b.x; acc[0][1] += a0 * b.y; acc[0][2] += a0 * b.z; acc[0][3] += a0 * b.w;
            acc[1][0] += a1 * b.x; acc[1][1] += a1 * b.y; acc[1][2] += a1 * b.z; acc[1][3] += a1 * b.w;
            acc[2][0] += a2 * b.x; acc[2][1] += a2 * b.y; acc[2][2] += a2 * b.z; acc[2][3] += a2 * b.w;
            acc[3][0] += a3 * b.x; acc[3][1] += a3 * b.y; acc[3][2] += a3 * b.z; acc[3][3] += a3 * b.w;
        }
        __syncthreads();
    }
#pragma unroll
    for (int i = 0; i < 4; i++) {
        int gr = rowbase + tr * 4 + i;
        if (gr < M) {
#pragma unroll
            for (int j = 0; j < 4; j++)
                C[(size_t)gr * N + colbase + tc * 4 + j] = acc[i][j];
        }
    }
}

// ---------------- CSR build ----------------
__device__ __forceinline__ int edge_row(int e, const int* ei, const int* i2) {
    return (e < E_DIR) ? ei[E_DIR + e] : i2[(e - E_DIR) * 4 + 3];
}

__global__ void hist_kernel(const int* __restrict__ ei, const int* __restrict__ i2) {
    int e = blockIdx.x * blockDim.x + threadIdx.x;
    if (e >= E_TOT) return;
    atomicAdd(&g_count[edge_row(e, ei, i2)], 1);
}

// single block, 1024 threads, 40 contiguous counts per thread
__global__ void scan_kernel() {
    __shared__ int s[1024];
    const int CH = 40;
    int t = threadIdx.x;
    int base = t * CH;
    int sum = 0;
    for (int j = 0; j < CH; j++) {
        int i = base + j;
        sum += (i < N_ENT) ? g_count[i] : 0;
    }
    s[t] = sum;
    __syncthreads();
    for (int off = 1; off < 1024; off <<= 1) {
        int add = (t >= off) ? s[t - off] : 0;
        __syncthreads();
        s[t] += add;
        __syncthreads();
    }
    int run = s[t] - sum;
    for (int j = 0; j < CH; j++) {
        int i = base + j;
        if (i < N_ENT) {
            g_ptr[i] = run;
            run += g_count[i];
        }
    }
    if (t == 1023) g_ptr[N_ENT] = s[1023];
}

__global__ void scatter_kernel(const int* __restrict__ ei, const int* __restrict__ i2) {
    int e = blockIdx.x * blockDim.x + threadIdx.x;
    if (e >= E_TOT) return;
    int row = edge_row(e, ei, i2);
    int pos = g_ptr[row] + atomicAdd(&g_fill[row], 1);
    g_eidx[pos] = e;
}

// ---------------- per-entity / per-relation attention scalars ----------------
__global__ void qkern(const float* __restrict__ a_heads) {
    int w = (blockIdx.x * blockDim.x + threadIdx.x) >> 5;
    int lane = threadIdx.x & 31;
    if (w >= N_ENT) return;
    const float* base = &g_C1[(size_t)w * 768];
    float s1 = 0.f, s2 = 0.f;
#pragma unroll
    for (int j = 0; j < 8; j++) {
        float av = a_heads[lane * 8 + j];
        s1 += base[lane * 8 + j] * av;
        s2 += base[256 + lane * 8 + j] * av;
    }
    for (int o = 4; o; o >>= 1) {
        s1 += __shfl_xor_sync(0xffffffffu, s1, o);
        s2 += __shfl_xor_sync(0xffffffffu, s2, o);
    }
    if ((lane & 7) == 0) {
        g_q1[w * 4 + (lane >> 3)] = s1;
        g_q2[w * 4 + (lane >> 3)] = s2;
    }
}

__global__ void rakern(const float* __restrict__ a_heads) {
    int w = (blockIdx.x * blockDim.x + threadIdx.x) >> 5;
    int lane = threadIdx.x & 31;
    if (w >= N_REL) return;
    const float* base = &g_R3[w * 256];
    float s = 0.f;
#pragma unroll
    for (int j = 0; j < 8; j++) s += base[lane * 8 + j] * a_heads[lane * 8 + j];
    for (int o = 4; o; o >>= 1) s += __shfl_xor_sync(0xffffffffu, s, o);
    if ((lane & 7) == 0) g_ra[w * 4 + (lane >> 3)] = s;
}

__global__ void ykern(const float* __restrict__ out_a) {
    int w = (blockIdx.x * blockDim.x + threadIdx.x) >> 5;
    int lane = threadIdx.x & 31;
    if (w >= N_ENT) return;
    const float* base = &g_C2[(size_t)w * 512];
    float s1 = 0.f, s2 = 0.f;
#pragma unroll
    for (int j = 0; j < 8; j++) {
        float av = out_a[lane * 8 + j];
        s1 += base[lane * 8 + j] * av;
        s2 += base[256 + lane * 8 + j] * av;
    }
    for (int o = 16; o; o >>= 1) {
        s1 += __shfl_xor_sync(0xffffffffu, s1, o);
        s2 += __shfl_xor_sync(0xffffffffu, s2, o);
    }
    if (lane == 0) { g_y1[w] = s1; g_y2[w] = s2; }
}

__global__ void rwakern(const float* __restrict__ out_a) {
    int w = (blockIdx.x * blockDim.x + threadIdx.x) >> 5;
    int lane = threadIdx.x & 31;
    if (w >= N_REL) return;
    const float* base = &g_RW[w * 256];
    float s = 0.f;
#pragma unroll
    for (int j = 0; j < 8; j++) s += base[lane * 8 + j] * out_a[lane * 8 + j];
    for (int o = 16; o; o >>= 1) s += __shfl_xor_sync(0xffffffffu, s, o);
    if (lane == 0) g_rwa[w] = s;
}

// ---------------- layer-1 attention aggregation (single pass; softmax shift-invariant) ----------------
__global__ __launch_bounds__(256) void agg1_kernel(const int* __restrict__ ei,
                                                   const int* __restrict__ et,
                                                   const int* __restrict__ i2) {
    int warp = blockIdx.x * 8 + (threadIdx.x >> 5);
    int lane = threadIdx.x & 31;
    if (warp >= N_ENT) return;
    int row = warp;
    int beg = g_ptr[row], end = g_ptr[row + 1];

    int hl = lane >> 3;
    int off = lane * 8;
    float qh = g_q1[row * 4 + hl];

    float acc[8] = {0, 0, 0, 0, 0, 0, 0, 0};
    float S = 0.f;
    for (int i = beg; i < end; i++) {
        int e = g_eidx[i];
        int col, a, b, dir;
        if (e < E_DIR) { col = ei[e]; a = et[e]; b = 0; dir = 1; }
        else { int j = e - E_DIR; col = i2[j * 4]; a = i2[j * 4 + 1]; b = i2[j * 4 + 2]; dir = 0; }
        float ras = g_ra[a * 4 + hl] + (dir ? 0.f : g_ra[b * 4 + hl]);
        float l = lrelu(qh + g_q2[col * 4 + hl] + ras);
        float w = expf(l);
        S += w;
        const float* p2 = &g_C1[(size_t)col * 768 + 256 + off];
        float4 v0 = *(const float4*)p2, v1 = *(const float4*)(p2 + 4);
        const float* rr = &g_R3[a * 256 + off];
        float4 r0 = *(const float4*)rr, r1 = *(const float4*)(rr + 4);
        if (!dir) {
            const float* r2p = &g_R3[b * 256 + off];
            float4 s0 = *(const float4*)r2p, s1 = *(const float4*)(r2p + 4);
            r0.x += s0.x; r0.y += s0.y; r0.z += s0.z; r0.w += s0.w;
            r1.x += s1.x; r1.y += s1.y; r1.z += s1.z; r1.w += s1.w;
        }
        acc[0] += w * (v0.x + r0.x); acc[1] += w * (v0.y + r0.y);
        acc[2] += w * (v0.z + r0.z); acc[3] += w * (v0.w + r0.w);
        acc[4] += w * (v1.x + r1.x); acc[5] += w * (v1.y + r1.y);
        acc[6] += w * (v1.z + r1.z); acc[7] += w * (v1.w + r1.w);
    }

    const float* p1 = &g_C1[(size_t)row * 768 + off];
    float inv = 1.f / (S + 1e-16f);
#pragma unroll
    for (int j = 0; j < 8; j++) {
        float v = elu((S * p1[j] + acc[j]) * inv);
        __nv_bfloat16 h, l;
        bf16_split(v, h, l);
        g_Xh[(size_t)row * 256 + off + j] = h;
        g_Xl[(size_t)row * 256 + off + j] = l;
    }
}

// ---------------- layer-2 attention aggregation (single pass) ----------------
__global__ __launch_bounds__(256) void agg2_kernel(const int* __restrict__ ei,
                                                   const int* __restrict__ et,
                                                   const int* __restrict__ i2,
                                                   float* __restrict__ out) {
    int warp = blockIdx.x * 8 + (threadIdx.x >> 5);
    int lane = threadIdx.x & 31;
    if (warp >= N_ENT) return;
    int row = warp;
    int beg = g_ptr[row], end = g_ptr[row + 1];
    float y1r = g_y1[row];

    int off = lane * 8;
    float acc[8] = {0, 0, 0, 0, 0, 0, 0, 0};
    float S = 0.f;
    for (int i = beg; i < end; i++) {
        int e = g_eidx[i];
        int col, a, b, dir;
        if (e < E_DIR) { col = ei[e]; a = et[e]; b = 0; dir = 1; }
        else { int j = e - E_DIR; col = i2[j * 4]; a = i2[j * 4 + 1]; b = i2[j * 4 + 2]; dir = 0; }
        float rs = g_rwa[a] + (dir ? 0.f : g_rwa[b]);
        float l = lrelu(y1r + g_y2[col] + rs);
        float w = expf(l);
        S += w;
        const float* x2 = &g_C2[(size_t)col * 512 + 256 + off];
        float4 v0 = *(const float4*)x2, v1 = *(const float4*)(x2 + 4);
        const float* rr = &g_RW[a * 256 + off];
        float4 r0 = *(const float4*)rr, r1 = *(const float4*)(rr + 4);
        if (!dir) {
            const float* r2p = &g_RW[b * 256 + off];
            float4 s0 = *(const float4*)r2p, s1 = *(const float4*)(r2p + 4);
            r0.x += s0.x; r0.y += s0.y; r0.z += s0.z; r0.w += s0.w;
            r1.x += s1.x; r1.y += s1.y; r1.z += s1.z; r1.w += s1.w;
        }
        acc[0] += w * (v0.x + r0.x); acc[1] += w * (v0.y + r0.y);
        acc[2] += w * (v0.z + r0.z); acc[3] += w * (v0.w + r0.w);
        acc[4] += w * (v1.x + r1.x); acc[5] += w * (v1.y + r1.y);
        acc[6] += w * (v1.z + r1.z); acc[7] += w * (v1.w + r1.w);
    }

    const float* x1 = &g_C2[(size_t)row * 512 + off];
    const float* ent = &g_C1[(size_t)row * 768 + 512 + off];
    float inv = 1.f / (S + 1e-16f);
#pragma unroll
    for (int j = 0; j < 8; j++) {
        float v = (S * x1[j] + acc[j]) * inv;
        out[(size_t)row * 256 + off + j] = elu(v) + ent[j];
    }
}

// ---------------- batch norm ----------------
__global__ void bnstats_kernel(const float* __restrict__ xo) {
    int c = threadIdx.x;
    float s = 0.f, s2 = 0.f;
    for (int row = blockIdx.x; row < N_ENT; row += gridDim.x) {
        float v = xo[(size_t)row * 256 + c];
        s += v; s2 += v * v;
    }
    atomicAdd(&g_bnsum[c], s);
    atomicAdd(&g_bnsq[c], s2);
}

__global__ void bnnorm_kernel(float* __restrict__ xo,
                              const float* __restrict__ gamma,
                              const float* __restrict__ beta) {
    size_t i = (size_t)blockIdx.x * blockDim.x + threadIdx.x;
    if (i >= (size_t)N_ENT * 256) return;
    int c = (int)(i & 255);
    float mu = g_bnsum[c] * (1.f / N_ENT);
    float var = g_bnsq[c] * (1.f / N_ENT) - mu * mu;
    float istd = rsqrtf(var + 1e-5f);
    float v = xo[i];
    xo[i] = (v - mu) * istd * gamma[c] + beta[c];
}

// ---------------- launch ----------------
extern "C" void kernel_launch(void* const* d_in, const int* in_sizes, int n_in,
                              void* d_out, int out_size) {
    const int*   edge_index = (const int*)d_in[0];
    const int*   edge_type  = (const int*)d_in[1];
    const int*   i2         = (const int*)d_in[2];
    const float* init_embed = (const float*)d_in[3];
    const float* init_rel   = (const float*)d_in[4];
    const float* W_heads    = (const float*)d_in[5];
    const float* a_heads    = (const float*)d_in[6];
    const float* gat_W      = (const float*)d_in[7];
    const float* out_W      = (const float*)d_in[8];
    const float* out_a      = (const float*)d_in[9];
    const float* W_ent      = (const float*)d_in[10];
    const float* gamma      = (const float*)d_in[11];
    const float* beta       = (const float*)d_in[12];

    float* out   = (float*)d_out;
    float* r_out = out + (size_t)N_ENT * 256;

    float *pC1, *pC2, *pR3, *pRW, *pB3;
    __nv_bfloat16 *pEh, *pEl, *pXh, *pXl, *pB1th, *pB1tl, *pO12th, *pO12tl;
    cudaGetSymbolAddress((void**)&pC1,    g_C1);
    cudaGetSymbolAddress((void**)&pC2,    g_C2);
    cudaGetSymbolAddress((void**)&pR3,    g_R3);
    cudaGetSymbolAddress((void**)&pRW,    g_RW);
    cudaGetSymbolAddress((void**)&pB3,    g_B3);
    cudaGetSymbolAddress((void**)&pEh,    g_Eh);
    cudaGetSymbolAddress((void**)&pEl,    g_El);
    cudaGetSymbolAddress((void**)&pXh,    g_Xh);
    cudaGetSymbolAddress((void**)&pXl,    g_Xl);
    cudaGetSymbolAddress((void**)&pB1th,  g_B1th);
    cudaGetSymbolAddress((void**)&pB1tl,  g_B1tl);
    cudaGetSymbolAddress((void**)&pO12th, g_O12th);
    cudaGetSymbolAddress((void**)&pO12tl, g_O12tl);

    static bool attr_set = false;
    if (!attr_set) {
        cudaFuncSetAttribute(gemm_mma, cudaFuncAttributeMaxDynamicSharedMemorySize, GSM_TOTAL);
        attr_set = true;
    }

    zero_kernel<<<(N_ENT + 256) / 256, 256>>>();
    split_embed_kernel<<<(N_ENT * 128 + 255) / 256, 256>>>(init_embed);
    assemble_kernel<<<(768 * 128 + 128 * 256 + 512 * 256 + 255) / 256, 256>>>(W_heads, W_ent, out_W);

    // CSR build
    hist_kernel<<<(E_TOT + 255) / 256, 256>>>(edge_index, i2);
    scan_kernel<<<1, 1024>>>();
    scatter_kernel<<<(E_TOT + 255) / 256, 256>>>(edge_index, i2);

    // big GEMM 1: C1[40000,768] = embed[40000,128] @ B1
    gemm_mma<<<dim3(768 / 128, (N_ENT + 127) / 128), 256, GSM_TOTAL>>>(pEh, pEl, pB1th, pB1tl, pC1, N_ENT, 768, 128);
    // small relation GEMMs (fp32 SIMT)
    sgemm<<<dim3(256 / 64, (N_REL + 63) / 64), 256>>>(init_rel, pB3, pR3, N_REL, 256, 128);
    sgemm<<<dim3(256 / 64, (N_REL + 63) / 64), 256>>>(init_rel, gat_W, r_out, N_REL, 256, 128);

    // layer-1 scalars + aggregation (writes Xh/Xl bf16 splits)
    qkern<<<(N_ENT * 32 + 255) / 256, 256>>>(a_heads);
    rakern<<<(N_REL * 32 + 255) / 256, 256>>>(a_heads);
    agg1_kernel<<<N_ENT / 8, 256>>>(edge_index, edge_type, i2);

    // big GEMM 2: C2[40000,512] = X[40000,256] @ O12
    gemm_mma<<<dim3(512 / 128, (N_ENT + 127) / 128), 256, GSM_TOTAL>>>(pXh, pXl, pO12th, pO12tl, pC2, N_ENT, 512, 256);
    sgemm<<<dim3(256 / 64, (N_REL + 63) / 64), 256>>>(r_out, out_W + 512 * 256, pRW, N_REL, 256, 256);
    ykern<<<(N_ENT * 32 + 255) / 256, 256>>>(out_a);
    rwakern<<<(N_REL * 32 + 255) / 256, 256>>>(out_a);
    agg2_kernel<<<N_ENT / 8, 256>>>(edge_index, edge_type, i2, out);

    // batch norm
    bnstats_kernel<<<512, 256>>>(out);
    bnnorm_kernel<<<(N_ENT * 256 + 255) / 256, 256>>>(out, gamma, beta);
}